// round 1
// baseline (speedup 1.0000x reference)
#include <cuda_runtime.h>
#include <math.h>

// ---------------- problem dims ----------------
#define BB      2
#define LSEQ    2048
#define DMODEL  1024
#define DINNER  2048
#define DSTATE  16
#define DTRANK  64
#define DCONVK  4
#define MROWS   (BB*LSEQ)          // 4096

// ---------------- scratch (device globals; no allocation allowed) ----------------
__device__ __align__(16) float g_xr   [(size_t)BB*LSEQ*2*DINNER]; // (b,l,4096): [0:2048)=xs, [2048:4096)=res
__device__ __align__(16) float g_u    [(size_t)BB*LSEQ*DINNER];   // post-conv silu
__device__ __align__(16) float g_xdbl [(size_t)BB*LSEQ*96];       // dt(64) | B(16) | C(16)
__device__ __align__(16) float g_delta[(size_t)BB*LSEQ*DINNER];
__device__ __align__(16) float g_y    [(size_t)BB*LSEQ*DINNER];

// ---------------- generic NT GEMM: C[m,n] = sum_k A[m,k]*B[n,k] ----------------
// EPI 0: plain store. EPI 1: softplus(x + bias[n]).
template<int BM, int BN, int BK, int TM, int TN, int EPI>
__global__ __launch_bounds__(256) void gemm_nt(
    const float* __restrict__ A, int lda,
    const float* __restrict__ Bm, int ldb,
    const float* __restrict__ bias,
    float* __restrict__ C, int ldc,
    int M, int N, int K)
{
    __shared__ float As[BK][BM + 4];
    __shared__ float Bs[BK][BN + 4];

    const int tid = threadIdx.x;
    const int m0 = blockIdx.y * BM;
    const int n0 = blockIdx.x * BN;
    const int tx = tid % (BN / TN);
    const int ty = tid / (BN / TN);
    const int kvecs = BK / 4;

    float acc[TM][TN];
#pragma unroll
    for (int i = 0; i < TM; i++)
#pragma unroll
        for (int j = 0; j < TN; j++) acc[i][j] = 0.f;

    for (int k0 = 0; k0 < K; k0 += BK) {
        // load A tile (rows always in bounds: M multiple of BM by construction)
        for (int t = tid; t < BM * kvecs; t += 256) {
            int row = t / kvecs;
            int col = (t % kvecs) * 4;
            const float4 v = *reinterpret_cast<const float4*>(
                A + (size_t)(m0 + row) * lda + k0 + col);
            As[col + 0][row] = v.x; As[col + 1][row] = v.y;
            As[col + 2][row] = v.z; As[col + 3][row] = v.w;
        }
        // load B tile with N guard
        for (int t = tid; t < BN * kvecs; t += 256) {
            int row = t / kvecs;
            int col = (t % kvecs) * 4;
            float4 v = make_float4(0.f, 0.f, 0.f, 0.f);
            if (n0 + row < N)
                v = *reinterpret_cast<const float4*>(
                    Bm + (size_t)(n0 + row) * ldb + k0 + col);
            Bs[col + 0][row] = v.x; Bs[col + 1][row] = v.y;
            Bs[col + 2][row] = v.z; Bs[col + 3][row] = v.w;
        }
        __syncthreads();

#pragma unroll
        for (int k = 0; k < BK; k++) {
            float a[TM], b[TN];
#pragma unroll
            for (int i = 0; i < TM; i++) a[i] = As[k][ty * TM + i];
#pragma unroll
            for (int j = 0; j < TN; j++) b[j] = Bs[k][tx * TN + j];
#pragma unroll
            for (int i = 0; i < TM; i++)
#pragma unroll
                for (int j = 0; j < TN; j++)
                    acc[i][j] = fmaf(a[i], b[j], acc[i][j]);
        }
        __syncthreads();
    }

#pragma unroll
    for (int i = 0; i < TM; i++) {
        int m = m0 + ty * TM + i;
#pragma unroll
        for (int j = 0; j < TN; j++) {
            int n = n0 + tx * TN + j;
            if (n < N) {
                float v = acc[i][j];
                if (EPI == 1) {
                    v += bias[n];
                    // stable softplus: max(x,0) + log1p(exp(-|x|))
                    v = fmaxf(v, 0.f) + log1pf(__expf(-fabsf(v)));
                }
                C[(size_t)m * ldc + n] = v;
            }
        }
    }
}

// ---------------- causal depthwise conv (k=4) + bias + SiLU ----------------
__global__ __launch_bounds__(256) void conv_silu_kernel(
    const float* __restrict__ cw,   // (DINNER,1,4)
    const float* __restrict__ cb,   // (DINNER)
    const float* __restrict__ xr,   // (b,l,4096), xs in cols [0,2048)
    float* __restrict__ u)          // (b,l,2048)
{
    int idx = blockIdx.x * blockDim.x + threadIdx.x;   // < B*L*DINNER
    int d  = idx & (DINNER - 1);
    int bl = idx >> 11;
    int l  = bl & (LSEQ - 1);

    const float4 w = *reinterpret_cast<const float4*>(cw + (size_t)d * 4);
    float acc = cb[d];
    float tap[4] = {w.x, w.y, w.z, w.w};
#pragma unroll
    for (int j = 0; j < 4; j++) {
        int ll = l - 3 + j;
        if (ll >= 0)
            acc = fmaf(xr[((size_t)(bl - 3 + j)) * (2 * DINNER) + d], tap[j], acc);
    }
    u[idx] = acc / (1.f + __expf(-acc));   // silu
}

// ---------------- fused selective scan + skip + gate ----------------
// 16 lanes per channel (b,d); lane n holds state h_n. 64-step smem windows.
__global__ __launch_bounds__(256) void scan_kernel(
    const float* __restrict__ delta,   // (b,l,DINNER)
    const float* __restrict__ u,       // (b,l,DINNER)
    const float* __restrict__ xdbl,    // (b,l,96): B at 64..79, C at 80..95
    const float* __restrict__ A_log,   // (DINNER,16)
    const float* __restrict__ Dvec,    // (DINNER)
    const float* __restrict__ xr,      // res in cols [2048,4096)
    float* __restrict__ y)             // (b,l,DINNER)
{
    const int LW = 64;
    __shared__ float sB[LW][16];
    __shared__ float sC[LW][16];
    __shared__ float sd[LW][16];
    __shared__ float su[LW][16];
    __shared__ float sy[LW][16];

    const int tid = threadIdx.x;
    const int g = tid >> 4;            // channel group within block (0..15)
    const int n = tid & 15;            // state index
    const int blk = blockIdx.x;        // 0..255
    const int b = blk >> 7;            // 128 blocks per batch
    const int dbase = (blk & 127) << 4;
    const int d = dbase + g;

    const float An = -__expf(A_log[(size_t)d * DSTATE + n]);
    const float Dd = Dvec[d];
    float h = 0.f;
    const size_t rowL = (size_t)b * LSEQ;

    for (int l0 = 0; l0 < LSEQ; l0 += LW) {
        // stage B,C (64 x 32 contiguous floats per row)
#pragma unroll
        for (int i = 0; i < 8; i++) {
            int idx = tid + i * 256;             // 0..2047
            int l = idx >> 5, c = idx & 31;
            float v = xdbl[(rowL + l0 + l) * 96 + 64 + c];
            if (c < 16) sB[l][c] = v; else sC[l][c - 16] = v;
        }
        // stage delta, u (64 x 16)
#pragma unroll
        for (int i = 0; i < 4; i++) {
            int idx = tid + i * 256;             // 0..1023
            int l = idx >> 4, dd = idx & 15;
            size_t off = (rowL + l0 + l) * DINNER + dbase + dd;
            sd[l][dd] = delta[off];
            su[l][dd] = u[off];
        }
        __syncthreads();

#pragma unroll 4
        for (int l = 0; l < LW; l++) {
            float dl = sd[l][g];
            float ul = su[l][g];
            float a = __expf(dl * An);
            h = fmaf(a, h, dl * ul * sB[l][n]);
            float p = h * sC[l][n];
            p += __shfl_xor_sync(0xffffffffu, p, 1);
            p += __shfl_xor_sync(0xffffffffu, p, 2);
            p += __shfl_xor_sync(0xffffffffu, p, 4);
            p += __shfl_xor_sync(0xffffffffu, p, 8);
            if (n == 0) sy[l][g] = fmaf(ul, Dd, p);
        }
        __syncthreads();

        // flush: gate with silu(res), coalesced store
#pragma unroll
        for (int i = 0; i < 4; i++) {
            int idx = tid + i * 256;
            int l = idx >> 4, dd = idx & 15;
            size_t row = rowL + l0 + l;
            float r = xr[row * (2 * DINNER) + DINNER + dbase + dd];
            float gate = r / (1.f + __expf(-r));
            y[row * DINNER + dbase + dd] = sy[l][dd] * gate;
        }
        __syncthreads();
    }
}

// ---------------- launch ----------------
extern "C" void kernel_launch(void* const* d_in, const int* in_sizes, int n_in,
                              void* d_out, int out_size)
{
    const float* x         = (const float*)d_in[0];
    const float* in_proj_w = (const float*)d_in[1];
    const float* conv_w    = (const float*)d_in[2];
    const float* conv_b    = (const float*)d_in[3];
    const float* x_proj_w  = (const float*)d_in[4];
    const float* dt_proj_w = (const float*)d_in[5];
    const float* dt_proj_b = (const float*)d_in[6];
    const float* A_log     = (const float*)d_in[7];
    const float* Dv        = (const float*)d_in[8];
    const float* out_proj_w= (const float*)d_in[9];
    float* out = (float*)d_out;

    float *xr, *u, *xdbl, *delta, *y;
    cudaGetSymbolAddress((void**)&xr,    g_xr);
    cudaGetSymbolAddress((void**)&u,     g_u);
    cudaGetSymbolAddress((void**)&xdbl,  g_xdbl);
    cudaGetSymbolAddress((void**)&delta, g_delta);
    cudaGetSymbolAddress((void**)&y,     g_y);

    // 1) in_proj: xr(4096,4096) = x(4096,1024) @ W^T
    gemm_nt<128,128,16,8,8,0><<<dim3(2*DINNER/128, MROWS/128), 256>>>(
        x, DMODEL, in_proj_w, DMODEL, nullptr, xr, 2*DINNER,
        MROWS, 2*DINNER, DMODEL);

    // 2) depthwise causal conv + SiLU -> u
    conv_silu_kernel<<<(MROWS * DINNER) / 256, 256>>>(conv_w, conv_b, xr, u);

    // 3) x_proj: xdbl(4096,96) = u(4096,2048) @ W^T   (small-N tiles for occupancy)
    gemm_nt<64,32,16,4,2,0><<<dim3(3, MROWS/64), 256>>>(
        u, DINNER, x_proj_w, DINNER, nullptr, xdbl, 96,
        MROWS, 96, DINNER);

    // 4) dt_proj + bias + softplus -> delta(4096,2048)
    gemm_nt<128,128,16,8,8,1><<<dim3(DINNER/128, MROWS/128), 256>>>(
        xdbl, 96, dt_proj_w, DTRANK, dt_proj_b, delta, DINNER,
        MROWS, DINNER, DTRANK);

    // 5) fused selective scan + u*D skip + silu(res) gate -> y
    scan_kernel<<<BB * DINNER / 16, 256>>>(delta, u, xdbl, A_log, Dv, xr, y);

    // 6) out_proj: out(4096,1024) = y(4096,2048) @ W^T
    gemm_nt<128,128,16,8,8,0><<<dim3(DMODEL/128, MROWS/128), 256>>>(
        y, DINNER, out_proj_w, DINNER, nullptr, out, DMODEL,
        MROWS, DMODEL, DINNER);
}

// round 8
// speedup vs baseline: 1.4864x; 1.4864x over previous
#include <cuda_runtime.h>
#include <math.h>
#include <stdint.h>

// ---------------- problem dims ----------------
#define BB      2
#define LSEQ    2048
#define DMODEL  1024
#define DINNER  2048
#define DSTATE  16
#define DTRANK  64
#define MROWS   (BB*LSEQ)          // 4096

// ---------------- scratch ----------------
__device__ __align__(16) float g_xr   [(size_t)MROWS*2*DINNER];
__device__ __align__(16) float g_u    [(size_t)MROWS*DINNER];
__device__ __align__(16) float g_xdbl [(size_t)MROWS*96];
__device__ __align__(16) float g_delta[(size_t)MROWS*DINNER];
__device__ __align__(16) float g_y    [(size_t)MROWS*DINNER];

// ---------------- helpers ----------------
__device__ __forceinline__ uint32_t s2u(const void* p){
    uint32_t a;
    asm("{ .reg .u64 t; cvta.to.shared.u64 t, %1; cvt.u32.u64 %0, t; }" : "=r"(a) : "l"(p));
    return a;
}
__device__ __forceinline__ void cp16(uint32_t dst, const void* src, uint32_t sz){
    asm volatile("cp.async.cg.shared.global [%0], [%1], 16, %2;"
        :: "r"(dst), "l"(src), "r"(sz) : "memory");
}
#define CP_COMMIT() asm volatile("cp.async.commit_group;" ::: "memory")
#define CP_WAIT(n)  asm volatile("cp.async.wait_group %0;" :: "n"(n) : "memory")

__device__ __forceinline__ void mma_tf32(float* d, const uint32_t* a, const uint32_t* b){
    asm volatile(
        "mma.sync.aligned.m16n8k8.row.col.f32.tf32.tf32.f32 "
        "{%0,%1,%2,%3}, {%4,%5,%6,%7}, {%8,%9}, {%0,%1,%2,%3};"
        : "+f"(d[0]), "+f"(d[1]), "+f"(d[2]), "+f"(d[3])
        : "r"(a[0]), "r"(a[1]), "r"(a[2]), "r"(a[3]), "r"(b[0]), "r"(b[1]));
}

// ================= 3xTF32 mma.sync GEMM: C[m,n] = sum_k A[m,k]*B[n,k] =================
// BM=128, BN=128, BK=32. 256 threads = 8 warps (2x4); warp tile 64x32.
// Each operand split hi/lo: hi = bits&0xFFFFE000 (exact tf32), lo = f - hi (exact fp32;
// HW truncates its low bits when used as tf32). D += hi*hi + hi*lo + lo*hi.
// EPI 0: plain store. EPI 1: softplus(x + bias[n]).
#define GSTRIDE 36                      // smem row stride in floats (128B rows + 16B pad)
#define STAGEF  (2*128*GSTRIDE)         // floats per stage (A tile + B tile)

template<int EPI>
__global__ __launch_bounds__(256)
void gemm_mma(const float* __restrict__ A, int lda,
              const float* __restrict__ Bw, int ldb,
              const float* __restrict__ bias,
              float* __restrict__ C, int ldc,
              int K, int N)
{
    extern __shared__ __align__(16) float sm[];

    const int tid  = threadIdx.x;
    const int warp = tid >> 5;
    const int lane = tid & 31;
    const int wm   = warp >> 2;         // 0..1
    const int wn   = warp & 3;          // 0..3
    const int g    = lane >> 2;         // 0..7
    const int t    = lane & 3;          // 0..3
    const int m0   = blockIdx.y * 128;
    const int n0   = blockIdx.x * 128;
    const int KT   = K / 32;

    float acc[4][4][4];
#pragma unroll
    for (int i = 0; i < 4; i++)
#pragma unroll
        for (int j = 0; j < 4; j++)
#pragma unroll
            for (int r = 0; r < 4; r++) acc[i][j][r] = 0.f;

    // ---- async tile loader: A tile 128x32 -> sm[s][0..], B tile 128x32 -> sm[s][A..]
    auto load_tile = [&](int kt, int s){
        const int k0 = kt * 32;
        float* As = sm + s * STAGEF;
        float* Bs = As + 128 * GSTRIDE;
#pragma unroll
        for (int i = 0; i < 4; i++) {
            int idx = tid + i * 256;          // 0..1023
            int r = idx >> 3;                 // 0..127
            int c = (idx & 7) * 4;            // 0,4,..,28
            cp16(s2u(As + r * GSTRIDE + c), A + (size_t)(m0 + r) * lda + k0 + c, 16);
            int gn = n0 + r;
            int rr = gn < N ? gn : (N - 1);
            cp16(s2u(Bs + r * GSTRIDE + c), Bw + (size_t)rr * ldb + k0 + c,
                 gn < N ? 16u : 0u);          // OOB rows zero-filled
        }
        CP_COMMIT();
    };

    load_tile(0, 0);

    for (int kt = 0; kt < KT; kt++) {
        const int s = kt & 1;
        if (kt + 1 < KT) { load_tile(kt + 1, s ^ 1); CP_WAIT(1); }
        else             { CP_WAIT(0); }
        __syncthreads();

        const float* As = sm + s * STAGEF;
        const float* Bs = As + 128 * GSTRIDE;

#pragma unroll
        for (int ks = 0; ks < 4; ks++) {
            const int k0 = ks * 8;
            uint32_t ahi[4][4], alo[4][4], bhi[4][2], blo[4][2];
#pragma unroll
            for (int mt = 0; mt < 4; mt++) {
                int mb = wm * 64 + mt * 16;
#pragma unroll
                for (int r = 0; r < 4; r++) {
                    int row = mb + (r & 1) * 8 + g;
                    int col = k0 + (r >> 1) * 4 + t;
                    float f = As[row * GSTRIDE + col];
                    uint32_t h = __float_as_uint(f) & 0xFFFFE000u;
                    ahi[mt][r] = h;
                    alo[mt][r] = __float_as_uint(f - __uint_as_float(h));
                }
            }
#pragma unroll
            for (int nt = 0; nt < 4; nt++) {
                int nb = wn * 32 + nt * 8 + g;
#pragma unroll
                for (int r = 0; r < 2; r++) {
                    float f = Bs[nb * GSTRIDE + k0 + r * 4 + t];
                    uint32_t h = __float_as_uint(f) & 0xFFFFE000u;
                    bhi[nt][r] = h;
                    blo[nt][r] = __float_as_uint(f - __uint_as_float(h));
                }
            }
#pragma unroll
            for (int mt = 0; mt < 4; mt++)
#pragma unroll
                for (int nt = 0; nt < 4; nt++) {
                    mma_tf32(acc[mt][nt], ahi[mt], bhi[nt]);
                    mma_tf32(acc[mt][nt], ahi[mt], blo[nt]);
                    mma_tf32(acc[mt][nt], alo[mt], bhi[nt]);
                }
        }
        __syncthreads();
    }

    // ---- epilogue: registers -> gmem (float2 per row-pair) ----
#pragma unroll
    for (int mt = 0; mt < 4; mt++) {
#pragma unroll
        for (int nt = 0; nt < 4; nt++) {
            int row0 = m0 + wm * 64 + mt * 16 + g;
            int col  = n0 + wn * 32 + nt * 8 + t * 2;
            if (col < N) {
                float2 v0 = make_float2(acc[mt][nt][0], acc[mt][nt][1]);
                float2 v1 = make_float2(acc[mt][nt][2], acc[mt][nt][3]);
                if (EPI == 1) {
                    float b0 = bias[col], b1 = bias[col + 1];
                    float x;
                    x = v0.x + b0; v0.x = fmaxf(x,0.f) + log1pf(__expf(-fabsf(x)));
                    x = v0.y + b1; v0.y = fmaxf(x,0.f) + log1pf(__expf(-fabsf(x)));
                    x = v1.x + b0; v1.x = fmaxf(x,0.f) + log1pf(__expf(-fabsf(x)));
                    x = v1.y + b1; v1.y = fmaxf(x,0.f) + log1pf(__expf(-fabsf(x)));
                }
                *reinterpret_cast<float2*>(C + (size_t)row0 * ldc + col) = v0;
                *reinterpret_cast<float2*>(C + (size_t)(row0 + 8) * ldc + col) = v1;
            }
        }
    }
}

// ---------------- causal depthwise conv (k=4) + bias + SiLU ----------------
__global__ __launch_bounds__(256) void conv_silu_kernel(
    const float* __restrict__ cw, const float* __restrict__ cb,
    const float* __restrict__ xr, float* __restrict__ u)
{
    int idx = blockIdx.x * blockDim.x + threadIdx.x;
    int d  = idx & (DINNER - 1);
    int bl = idx >> 11;
    int l  = bl & (LSEQ - 1);
    const float4 w = *reinterpret_cast<const float4*>(cw + (size_t)d * 4);
    float acc = cb[d];
    float tap[4] = {w.x, w.y, w.z, w.w};
#pragma unroll
    for (int j = 0; j < 4; j++) {
        int ll = l - 3 + j;
        if (ll >= 0)
            acc = fmaf(xr[((size_t)(bl - 3 + j)) * (2 * DINNER) + d], tap[j], acc);
    }
    u[idx] = acc / (1.f + __expf(-acc));
}

// ---------------- fused selective scan + skip + gate ----------------
__global__ __launch_bounds__(256) void scan_kernel(
    const float* __restrict__ delta, const float* __restrict__ u,
    const float* __restrict__ xdbl,  const float* __restrict__ A_log,
    const float* __restrict__ Dvec,  const float* __restrict__ xr,
    float* __restrict__ y)
{
    const int LW = 64;
    __shared__ float sB[LW][16];
    __shared__ float sC[LW][16];
    __shared__ float sd[LW][16];
    __shared__ float su[LW][16];
    __shared__ float sy[LW][16];

    const int tid = threadIdx.x;
    const int g = tid >> 4;
    const int n = tid & 15;
    const int blk = blockIdx.x;
    const int b = blk >> 7;
    const int dbase = (blk & 127) << 4;
    const int d = dbase + g;

    const float An = -__expf(A_log[(size_t)d * DSTATE + n]);
    const float Dd = Dvec[d];
    float h = 0.f;
    const size_t rowL = (size_t)b * LSEQ;

    for (int l0 = 0; l0 < LSEQ; l0 += LW) {
#pragma unroll
        for (int i = 0; i < 8; i++) {
            int idx = tid + i * 256;
            int l = idx >> 5, c = idx & 31;
            float v = xdbl[(rowL + l0 + l) * 96 + 64 + c];
            if (c < 16) sB[l][c] = v; else sC[l][c - 16] = v;
        }
#pragma unroll
        for (int i = 0; i < 4; i++) {
            int idx = tid + i * 256;
            int l = idx >> 4, dd = idx & 15;
            size_t off = (rowL + l0 + l) * DINNER + dbase + dd;
            sd[l][dd] = delta[off];
            su[l][dd] = u[off];
        }
        __syncthreads();

#pragma unroll 4
        for (int l = 0; l < LW; l++) {
            float dl = sd[l][g];
            float ul = su[l][g];
            float a = __expf(dl * An);
            h = fmaf(a, h, dl * ul * sB[l][n]);
            float p = h * sC[l][n];
            p += __shfl_xor_sync(0xffffffffu, p, 1);
            p += __shfl_xor_sync(0xffffffffu, p, 2);
            p += __shfl_xor_sync(0xffffffffu, p, 4);
            p += __shfl_xor_sync(0xffffffffu, p, 8);
            if (n == 0) sy[l][g] = fmaf(ul, Dd, p);
        }
        __syncthreads();

#pragma unroll
        for (int i = 0; i < 4; i++) {
            int idx = tid + i * 256;
            int l = idx >> 4, dd = idx & 15;
            size_t row = rowL + l0 + l;
            float r = xr[row * (2 * DINNER) + DINNER + dbase + dd];
            float gate = r / (1.f + __expf(-r));
            y[row * DINNER + dbase + dd] = sy[l][dd] * gate;
        }
        __syncthreads();
    }
}

// ---------------- launch ----------------
extern "C" void kernel_launch(void* const* d_in, const int* in_sizes, int n_in,
                              void* d_out, int out_size)
{
    const float* x         = (const float*)d_in[0];
    const float* in_proj_w = (const float*)d_in[1];
    const float* conv_w    = (const float*)d_in[2];
    const float* conv_b    = (const float*)d_in[3];
    const float* x_proj_w  = (const float*)d_in[4];
    const float* dt_proj_w = (const float*)d_in[5];
    const float* dt_proj_b = (const float*)d_in[6];
    const float* A_log     = (const float*)d_in[7];
    const float* Dv        = (const float*)d_in[8];
    const float* out_proj_w= (const float*)d_in[9];
    float* out = (float*)d_out;

    float *xr, *u, *xdbl, *delta, *y;
    cudaGetSymbolAddress((void**)&xr,    g_xr);
    cudaGetSymbolAddress((void**)&u,     g_u);
    cudaGetSymbolAddress((void**)&xdbl,  g_xdbl);
    cudaGetSymbolAddress((void**)&delta, g_delta);
    cudaGetSymbolAddress((void**)&y,     g_y);

    const int SMEMB = 2 * STAGEF * 4;   // 73728 bytes
    cudaFuncSetAttribute(gemm_mma<0>, cudaFuncAttributeMaxDynamicSharedMemorySize, SMEMB);
    cudaFuncSetAttribute(gemm_mma<1>, cudaFuncAttributeMaxDynamicSharedMemorySize, SMEMB);

    // 1) in_proj: xr(4096,4096) = x(4096,1024) @ W^T
    gemm_mma<0><<<dim3(32, 32), 256, SMEMB>>>(
        x, DMODEL, in_proj_w, DMODEL, nullptr, xr, 2*DINNER, DMODEL, 2*DINNER);

    // 2) depthwise causal conv + SiLU -> u
    conv_silu_kernel<<<(MROWS * DINNER) / 256, 256>>>(conv_w, conv_b, xr, u);

    // 3) x_proj: xdbl(4096,96) = u(4096,2048) @ W^T  (N=96, tile guard + zero-fill)
    gemm_mma<0><<<dim3(1, 32), 256, SMEMB>>>(
        u, DINNER, x_proj_w, DINNER, nullptr, xdbl, 96, DINNER, 96);

    // 4) dt_proj + bias + softplus -> delta(4096,2048)   (K=64, lda=96)
    gemm_mma<1><<<dim3(16, 32), 256, SMEMB>>>(
        xdbl, 96, dt_proj_w, DTRANK, dt_proj_b, delta, DINNER, DTRANK, DINNER);

    // 5) fused selective scan + skip + gate -> y
    scan_kernel<<<BB * DINNER / 16, 256>>>(delta, u, xdbl, A_log, Dv, xr, y);

    // 6) out_proj: out(4096,1024) = y(4096,2048) @ W^T
    gemm_mma<0><<<dim3(8, 32), 256, SMEMB>>>(
        y, DINNER, out_proj_w, DINNER, nullptr, out, DMODEL, DINNER, DMODEL);
}

// round 13
// speedup vs baseline: 1.6892x; 1.1365x over previous
#include <cuda_runtime.h>
#include <math.h>
#include <stdint.h>

// ---------------- problem dims ----------------
#define BB      2
#define LSEQ    2048
#define DMODEL  1024
#define DINNER  2048
#define DSTATE  16
#define DTRANK  64
#define MROWS   (BB*LSEQ)          // 4096

// ---------------- scratch ----------------
__device__ __align__(16) float g_xr   [(size_t)MROWS*2*DINNER];
__device__ __align__(16) float g_u    [(size_t)MROWS*DINNER];
__device__ __align__(16) float g_xdbl [(size_t)MROWS*96];
__device__ __align__(16) float g_delta[(size_t)MROWS*DINNER];
__device__ __align__(16) float g_y    [(size_t)MROWS*DINNER];

// ---------------- helpers ----------------
__device__ __forceinline__ uint32_t s2u(const void* p){
    uint32_t a;
    asm("{ .reg .u64 t; cvta.to.shared.u64 t, %1; cvt.u32.u64 %0, t; }" : "=r"(a) : "l"(p));
    return a;
}
__device__ __forceinline__ void cp16(uint32_t dst, const void* src, uint32_t sz){
    asm volatile("cp.async.cg.shared.global [%0], [%1], 16, %2;"
        :: "r"(dst), "l"(src), "r"(sz) : "memory");
}
#define CP_COMMIT() asm volatile("cp.async.commit_group;" ::: "memory")
#define CP_WAIT(n)  asm volatile("cp.async.wait_group %0;" :: "n"(n) : "memory")

__device__ __forceinline__ void mma_tf32(float* d, const uint32_t* a, const uint32_t* b){
    asm volatile(
        "mma.sync.aligned.m16n8k8.row.col.f32.tf32.tf32.f32 "
        "{%0,%1,%2,%3}, {%4,%5,%6,%7}, {%8,%9}, {%0,%1,%2,%3};"
        : "+f"(d[0]), "+f"(d[1]), "+f"(d[2]), "+f"(d[3])
        : "r"(a[0]), "r"(a[1]), "r"(a[2]), "r"(a[3]), "r"(b[0]), "r"(b[1]));
}

__global__ void zero_kernel(float4* p, int n){
    int i = blockIdx.x * blockDim.x + threadIdx.x;
    if (i < n) p[i] = make_float4(0.f, 0.f, 0.f, 0.f);
}

// ================= 3xTF32 mma.sync GEMM: C[m,n] = sum_k A[m,k]*B[n,k] =================
// BM=128, BN=128, BK=32. 256 threads = 8 warps (2x4); warp tile 64x32.
// Split: hi = bits&0xFFFFE000 (exact tf32), lo = f-hi. D += hi*hi + hi*lo + lo*hi,
// issued pass-major so consecutive MMAs hit distinct accumulators.
// blockIdx.z = K-slice (split-K); K param = K per slice.
// EPI 0: plain store. EPI 1: softplus(x+bias[n]). EPI 2: atomicAdd (split-K).
#define GSTRIDE 36
#define STAGEF  (2*128*GSTRIDE)

template<int EPI>
__global__ __launch_bounds__(256, 2)
void gemm_mma(const float* __restrict__ A, int lda,
              const float* __restrict__ Bw, int ldb,
              const float* __restrict__ bias,
              float* __restrict__ C, int ldc,
              int K, int N)
{
    extern __shared__ __align__(16) float sm[];

    const int tid  = threadIdx.x;
    const int warp = tid >> 5;
    const int lane = tid & 31;
    const int wm   = warp >> 2;
    const int wn   = warp & 3;
    const int g    = lane >> 2;
    const int t    = lane & 3;
    const int m0   = blockIdx.y * 128;
    const int n0   = blockIdx.x * 128;
    const int kbase= blockIdx.z * K;
    const int KT   = K / 32;

    float acc[4][4][4];
#pragma unroll
    for (int i = 0; i < 4; i++)
#pragma unroll
        for (int j = 0; j < 4; j++)
#pragma unroll
            for (int r = 0; r < 4; r++) acc[i][j][r] = 0.f;

    auto load_tile = [&](int kt, int s){
        const int k0 = kbase + kt * 32;
        float* As = sm + s * STAGEF;
        float* Bs = As + 128 * GSTRIDE;
#pragma unroll
        for (int i = 0; i < 4; i++) {
            int idx = tid + i * 256;
            int r = idx >> 3;
            int c = (idx & 7) * 4;
            cp16(s2u(As + r * GSTRIDE + c), A + (size_t)(m0 + r) * lda + k0 + c, 16);
            int gn = n0 + r;
            int rr = gn < N ? gn : (N - 1);
            cp16(s2u(Bs + r * GSTRIDE + c), Bw + (size_t)rr * ldb + k0 + c,
                 gn < N ? 16u : 0u);
        }
        CP_COMMIT();
    };

    load_tile(0, 0);

    for (int kt = 0; kt < KT; kt++) {
        const int s = kt & 1;
        if (kt + 1 < KT) { load_tile(kt + 1, s ^ 1); CP_WAIT(1); }
        else             { CP_WAIT(0); }
        __syncthreads();

        const float* As = sm + s * STAGEF;
        const float* Bs = As + 128 * GSTRIDE;

#pragma unroll
        for (int ks = 0; ks < 4; ks++) {
            const int k0 = ks * 8;
            uint32_t ahi[4][4], alo[4][4], bhi[4][2], blo[4][2];
#pragma unroll
            for (int mt = 0; mt < 4; mt++) {
                int mb = wm * 64 + mt * 16;
#pragma unroll
                for (int r = 0; r < 4; r++) {
                    int row = mb + (r & 1) * 8 + g;
                    int col = k0 + (r >> 1) * 4 + t;
                    float f = As[row * GSTRIDE + col];
                    uint32_t h = __float_as_uint(f) & 0xFFFFE000u;
                    ahi[mt][r] = h;
                    alo[mt][r] = __float_as_uint(f - __uint_as_float(h));
                }
            }
#pragma unroll
            for (int nt = 0; nt < 4; nt++) {
                int nb = wn * 32 + nt * 8 + g;
#pragma unroll
                for (int r = 0; r < 2; r++) {
                    float f = Bs[nb * GSTRIDE + k0 + r * 4 + t];
                    uint32_t h = __float_as_uint(f) & 0xFFFFE000u;
                    bhi[nt][r] = h;
                    blo[nt][r] = __float_as_uint(f - __uint_as_float(h));
                }
            }
            // pass-major: 16 independent accumulators between same-acc reuse
#pragma unroll
            for (int mt = 0; mt < 4; mt++)
#pragma unroll
                for (int nt = 0; nt < 4; nt++)
                    mma_tf32(acc[mt][nt], ahi[mt], bhi[nt]);
#pragma unroll
            for (int mt = 0; mt < 4; mt++)
#pragma unroll
                for (int nt = 0; nt < 4; nt++)
                    mma_tf32(acc[mt][nt], ahi[mt], blo[nt]);
#pragma unroll
            for (int mt = 0; mt < 4; mt++)
#pragma unroll
                for (int nt = 0; nt < 4; nt++)
                    mma_tf32(acc[mt][nt], alo[mt], bhi[nt]);
        }
        __syncthreads();
    }

    // ---- epilogue ----
#pragma unroll
    for (int mt = 0; mt < 4; mt++) {
#pragma unroll
        for (int nt = 0; nt < 4; nt++) {
            int row0 = m0 + wm * 64 + mt * 16 + g;
            int col  = n0 + wn * 32 + nt * 8 + t * 2;
            if (col < N) {
                float2 v0 = make_float2(acc[mt][nt][0], acc[mt][nt][1]);
                float2 v1 = make_float2(acc[mt][nt][2], acc[mt][nt][3]);
                if (EPI == 1) {
                    float b0 = bias[col], b1 = bias[col + 1];
                    float x;
                    x = v0.x + b0; v0.x = fmaxf(x,0.f) + log1pf(__expf(-fabsf(x)));
                    x = v0.y + b1; v0.y = fmaxf(x,0.f) + log1pf(__expf(-fabsf(x)));
                    x = v1.x + b0; v1.x = fmaxf(x,0.f) + log1pf(__expf(-fabsf(x)));
                    x = v1.y + b1; v1.y = fmaxf(x,0.f) + log1pf(__expf(-fabsf(x)));
                }
                if (EPI == 2) {
                    float* c0 = C + (size_t)row0 * ldc + col;
                    float* c1 = C + (size_t)(row0 + 8) * ldc + col;
                    atomicAdd(c0,     v0.x); atomicAdd(c0 + 1, v0.y);
                    atomicAdd(c1,     v1.x); atomicAdd(c1 + 1, v1.y);
                } else {
                    *reinterpret_cast<float2*>(C + (size_t)row0 * ldc + col) = v0;
                    *reinterpret_cast<float2*>(C + (size_t)(row0 + 8) * ldc + col) = v1;
                }
            }
        }
    }
}

// ---------------- causal depthwise conv (k=4) + bias + SiLU ----------------
__global__ __launch_bounds__(256) void conv_silu_kernel(
    const float* __restrict__ cw, const float* __restrict__ cb,
    const float* __restrict__ xr, float* __restrict__ u)
{
    int idx = blockIdx.x * blockDim.x + threadIdx.x;
    int d  = idx & (DINNER - 1);
    int bl = idx >> 11;
    int l  = bl & (LSEQ - 1);
    const float4 w = *reinterpret_cast<const float4*>(cw + (size_t)d * 4);
    float acc = cb[d];
    float tap[4] = {w.x, w.y, w.z, w.w};
#pragma unroll
    for (int j = 0; j < 4; j++) {
        int ll = l - 3 + j;
        if (ll >= 0)
            acc = fmaf(xr[((size_t)(bl - 3 + j)) * (2 * DINNER) + d], tap[j], acc);
    }
    u[idx] = acc / (1.f + __expf(-acc));
}

// ---------------- fused selective scan + skip + gate ----------------
__global__ __launch_bounds__(256) void scan_kernel(
    const float* __restrict__ delta, const float* __restrict__ u,
    const float* __restrict__ xdbl,  const float* __restrict__ A_log,
    const float* __restrict__ Dvec,  const float* __restrict__ xr,
    float* __restrict__ y)
{
    const int LW = 64;
    __shared__ float sB[LW][16];
    __shared__ float sC[LW][16];
    __shared__ float sd[LW][16];
    __shared__ float su[LW][16];
    __shared__ float sy[LW][16];

    const int tid = threadIdx.x;
    const int g = tid >> 4;
    const int n = tid & 15;
    const int blk = blockIdx.x;
    const int b = blk >> 7;
    const int dbase = (blk & 127) << 4;
    const int d = dbase + g;

    const float An = -__expf(A_log[(size_t)d * DSTATE + n]);
    const float Dd = Dvec[d];
    float h = 0.f;
    const size_t rowL = (size_t)b * LSEQ;

    for (int l0 = 0; l0 < LSEQ; l0 += LW) {
#pragma unroll
        for (int i = 0; i < 8; i++) {
            int idx = tid + i * 256;
            int l = idx >> 5, c = idx & 31;
            float v = xdbl[(rowL + l0 + l) * 96 + 64 + c];
            if (c < 16) sB[l][c] = v; else sC[l][c - 16] = v;
        }
#pragma unroll
        for (int i = 0; i < 4; i++) {
            int idx = tid + i * 256;
            int l = idx >> 4, dd = idx & 15;
            size_t off = (rowL + l0 + l) * DINNER + dbase + dd;
            sd[l][dd] = delta[off];
            su[l][dd] = u[off];
        }
        __syncthreads();

#pragma unroll 4
        for (int l = 0; l < LW; l++) {
            float dl = sd[l][g];
            float ul = su[l][g];
            float a = __expf(dl * An);
            h = fmaf(a, h, dl * ul * sB[l][n]);
            float p = h * sC[l][n];
            p += __shfl_xor_sync(0xffffffffu, p, 1);
            p += __shfl_xor_sync(0xffffffffu, p, 2);
            p += __shfl_xor_sync(0xffffffffu, p, 4);
            p += __shfl_xor_sync(0xffffffffu, p, 8);
            if (n == 0) sy[l][g] = fmaf(ul, Dd, p);
        }
        __syncthreads();

#pragma unroll
        for (int i = 0; i < 4; i++) {
            int idx = tid + i * 256;
            int l = idx >> 4, dd = idx & 15;
            size_t row = rowL + l0 + l;
            float r = xr[row * (2 * DINNER) + DINNER + dbase + dd];
            float gate = r / (1.f + __expf(-r));
            y[row * DINNER + dbase + dd] = sy[l][dd] * gate;
        }
        __syncthreads();
    }
}

// ---------------- launch ----------------
extern "C" void kernel_launch(void* const* d_in, const int* in_sizes, int n_in,
                              void* d_out, int out_size)
{
    const float* x         = (const float*)d_in[0];
    const float* in_proj_w = (const float*)d_in[1];
    const float* conv_w    = (const float*)d_in[2];
    const float* conv_b    = (const float*)d_in[3];
    const float* x_proj_w  = (const float*)d_in[4];
    const float* dt_proj_w = (const float*)d_in[5];
    const float* dt_proj_b = (const float*)d_in[6];
    const float* A_log     = (const float*)d_in[7];
    const float* Dv        = (const float*)d_in[8];
    const float* out_proj_w= (const float*)d_in[9];
    float* out = (float*)d_out;

    float *xr, *u, *xdbl, *delta, *y;
    cudaGetSymbolAddress((void**)&xr,    g_xr);
    cudaGetSymbolAddress((void**)&u,     g_u);
    cudaGetSymbolAddress((void**)&xdbl,  g_xdbl);
    cudaGetSymbolAddress((void**)&delta, g_delta);
    cudaGetSymbolAddress((void**)&y,     g_y);

    const int SMEMB = 2 * STAGEF * 4;   // 73728 bytes
    cudaFuncSetAttribute(gemm_mma<0>, cudaFuncAttributeMaxDynamicSharedMemorySize, SMEMB);
    cudaFuncSetAttribute(gemm_mma<1>, cudaFuncAttributeMaxDynamicSharedMemorySize, SMEMB);
    cudaFuncSetAttribute(gemm_mma<2>, cudaFuncAttributeMaxDynamicSharedMemorySize, SMEMB);

    // 1) in_proj: xr(4096,4096) = x(4096,1024) @ W^T
    gemm_mma<0><<<dim3(32, 32), 256, SMEMB>>>(
        x, DMODEL, in_proj_w, DMODEL, nullptr, xr, 2*DINNER, DMODEL, 2*DINNER);

    // 2) depthwise causal conv + SiLU -> u
    conv_silu_kernel<<<(MROWS * DINNER) / 256, 256>>>(conv_w, conv_b, xr, u);

    // 3) x_proj: xdbl(4096,96) = u(4096,2048) @ W^T  — split-K x4 + atomic epilogue
    zero_kernel<<<(MROWS * 96 / 4 + 255) / 256, 256>>>((float4*)xdbl, MROWS * 96 / 4);
    gemm_mma<2><<<dim3(1, 32, 4), 256, SMEMB>>>(
        u, DINNER, x_proj_w, DINNER, nullptr, xdbl, 96, DINNER / 4, 96);

    // 4) dt_proj + bias + softplus -> delta(4096,2048)   (K=64, lda=96)
    gemm_mma<1><<<dim3(16, 32), 256, SMEMB>>>(
        xdbl, 96, dt_proj_w, DTRANK, dt_proj_b, delta, DINNER, DTRANK, DINNER);

    // 5) fused selective scan + skip + gate -> y
    scan_kernel<<<BB * DINNER / 16, 256>>>(delta, u, xdbl, A_log, Dv, xr, y);

    // 6) out_proj: out(4096,1024) = y(4096,2048) @ W^T
    gemm_mma<0><<<dim3(8, 32), 256, SMEMB>>>(
        y, DINNER, out_proj_w, DINNER, nullptr, out, DMODEL, DINNER, DMODEL);
}